// round 6
// baseline (speedup 1.0000x reference)
#include <cuda_runtime.h>
#include <math.h>

typedef unsigned long long ull;

// Problem constants
#define NB 8
#define SQ 4096
#define EE 1024
#define HH 16
#define NCHUNK 32
#define CHUNK 128

// Scratch (static device globals -- allocation-free per harness rules)
__device__ float g_qvec[EE];
__device__ float g_wqk[HH*EE];
__device__ float g_c[HH];
__device__ float g_logits[NB*HH*SQ];
__device__ float g_pm[NB*HH*SQ];
__device__ float g_A[NB*HH*SQ];
__device__ float g_psum[NB*HH];
__device__ float g_partial[NB*NCHUNK*HH*EE];   // 16.8 MB partial ctx
__device__ float g_ctx[NB*HH*EE];
__device__ float g_hidden[NB*EE];
__device__ float g_act[NB*4*EE];

__device__ __forceinline__ float warp_sum(float v){
    #pragma unroll
    for (int o=16;o;o>>=1) v += __shfl_xor_sync(0xffffffffu, v, o);
    return v;
}

// packed f32x2 helpers
__device__ __forceinline__ void ffma2(ull &d, ull a, ull b){
    asm("fma.rn.f32x2 %0, %1, %2, %0;" : "+l"(d) : "l"(a), "l"(b));
}
__device__ __forceinline__ ull fadd2(ull a, ull b){
    ull d; asm("add.rn.f32x2 %0, %1, %2;" : "=l"(d) : "l"(a), "l"(b)); return d;
}
__device__ __forceinline__ ull pk2(float x, float y){
    float2 t = make_float2(x,y); return *(ull*)&t;
}
__device__ __forceinline__ float2 upk(ull v){ return *(float2*)&v; }

__global__ void k_dummy(){}

// ---------------- K0a: qvec = Wq @ query + bq ----------------
__global__ void __launch_bounds__(256) k_qvec(const float4* __restrict__ Wq4,
                                              const float4* __restrict__ q4,
                                              const float*  __restrict__ bq){
    int lane = threadIdx.x & 31, warp = threadIdx.x >> 5;
    int row = blockIdx.x*8 + warp;
    float acc = 0.f;
    #pragma unroll
    for (int k=0;k<8;k++){
        float4 w = Wq4[row*256 + lane + 32*k];
        float4 q = q4[lane + 32*k];
        acc += w.x*q.x + w.y*q.y + w.z*q.z + w.w*q.w;
    }
    acc = warp_sum(acc);
    if (lane==0) g_qvec[row] = acc + bq[row];
}

// ---------------- K0b: w_qk[h,e] = 0.125*sum_d qv[d]*Wk[h*64+d,e]; c[h] ----------------
__global__ void __launch_bounds__(256) k_wqk(const float4* __restrict__ Wk4,
                                             const float*  __restrict__ bk){
    __shared__ float qv[64];
    __shared__ float4 red[8][32];
    int h = blockIdx.x>>3, es = blockIdx.x&7;
    int tid = threadIdx.x, col = tid&31, dg = tid>>5;
    if (tid < 64) qv[tid] = g_qvec[h*64+tid];
    __syncthreads();
    float4 acc = make_float4(0.f,0.f,0.f,0.f);
    #pragma unroll
    for (int j=0;j<8;j++){
        int d = dg*8+j;
        float w = qv[d];
        float4 kk = Wk4[(h*64+d)*256 + es*32 + col];
        acc.x += w*kk.x; acc.y += w*kk.y; acc.z += w*kk.z; acc.w += w*kk.w;
    }
    red[dg][col] = acc;
    __syncthreads();
    if (tid < 32){
        float4 s = red[0][tid];
        #pragma unroll
        for (int g=1;g<8;g++){
            float4 r = red[g][tid];
            s.x+=r.x; s.y+=r.y; s.z+=r.z; s.w+=r.w;
        }
        s.x*=0.125f; s.y*=0.125f; s.z*=0.125f; s.w*=0.125f;
        ((float4*)g_wqk)[h*256 + es*32 + tid] = s;
    }
    if (es==0 && tid==0){
        float c=0.f;
        for (int d=0;d<64;d++) c += qv[d]*bk[h*64+d];
        g_c[h] = 0.125f*c;
    }
}

// ---------------- K1: logits = w_qk·x + c ----------------
// 8 warps = 4 head-quads (hq) x 2 e-halves (eh). Thread: 4 heads x 16 e-floats,
// weights 32 ull e-pair packed (no dup), acc 4 ull. x via LDG (L1 reuse across
// the 4 hq warps). 6-shfl fold; one sync; coalesced epilogue.
__global__ void __launch_bounds__(256,2) k_logits(const float4* __restrict__ x4){
    __shared__ float sred[32][16][2];
    int tid = threadIdx.x, lane = tid&31, warp = tid>>5;
    int hq = warp>>1, eh = warp&1;
    ull w[4][4][2];
    {
        const float4* wq4 = (const float4*)g_wqk;
        #pragma unroll
        for (int k=0;k<4;k++){
            int F = eh*128 + lane + 32*k;
            #pragma unroll
            for (int hp=0;hp<4;hp++){
                float4 wv = wq4[(hq*4+hp)*256 + F];
                w[k][hp][0] = pk2(wv.x,wv.y);
                w[k][hp][1] = pk2(wv.z,wv.w);
            }
        }
    }
    int rowbase = blockIdx.x*32;
    int b = rowbase>>12;
    int hsel = ((lane>>4)&1)*2 + ((lane>>3)&1);
    bool hi16 = (lane&16)!=0, hi8 = (lane&8)!=0;
    bool writer = (lane&7)==0;

    #pragma unroll 2
    for (int r=0;r<32;r++){
        int row = rowbase + r;
        ull acc[4] = {0ULL,0ULL,0ULL,0ULL};
        #pragma unroll
        for (int k=0;k<4;k++){
            int F = eh*128 + lane + 32*k;
            float4 xv = __ldg(&x4[row*256 + F]);
            ull x01 = pk2(xv.x,xv.y), x23 = pk2(xv.z,xv.w);
            #pragma unroll
            for (int hp=0;hp<4;hp++){
                ffma2(acc[hp], w[k][hp][0], x01);
                ffma2(acc[hp], w[k][hp][1], x23);
            }
        }
        // fold 4->2 over xor16: low lanes keep h'0,1; high keep h'2,3
        ull s0 = hi16 ? acc[0] : acc[2];
        ull s1 = hi16 ? acc[1] : acc[3];
        s0 = __shfl_xor_sync(0xffffffffu, s0, 16);
        s1 = __shfl_xor_sync(0xffffffffu, s1, 16);
        ull a0 = fadd2(hi16 ? acc[2] : acc[0], s0);
        ull a1 = fadd2(hi16 ? acc[3] : acc[1], s1);
        // fold 2->1 over xor8
        ull s2 = hi8 ? a0 : a1;
        s2 = __shfl_xor_sync(0xffffffffu, s2, 8);
        ull a = fadd2(hi8 ? a1 : a0, s2);
        // butterfly over remaining 8-lane class
        a = fadd2(a, __shfl_xor_sync(0xffffffffu, a, 4));
        a = fadd2(a, __shfl_xor_sync(0xffffffffu, a, 2));
        a = fadd2(a, __shfl_xor_sync(0xffffffffu, a, 1));
        float2 f = upk(a);
        if (writer) sred[r][hq*4+hsel][eh] = f.x + f.y;
    }
    __syncthreads();
    {
        int h = tid>>4, rg = tid&15;
        float c = g_c[h];
        float v0 = sred[rg*2  ][h][0] + sred[rg*2  ][h][1] + c;
        float v1 = sred[rg*2+1][h][0] + sred[rg*2+1][h][1] + c;
        int sbase = (rowbase&4095) + rg*2;
        *(float2*)&g_logits[((b<<4)+h)*4096 + sbase] = make_float2(v0,v1);
    }
}

// ---------------- K2: softmax over S + gumbel hard mask, per (b,h) ----------------
__global__ void __launch_bounds__(256) k_softmax(const float2* __restrict__ gu2){
    __shared__ float red[8];
    __shared__ float bc;
    int bid = blockIdx.x;                 // b*16+h
    int tid = threadIdx.x, lane = tid&31, warp = tid>>5;
    int base = bid*4096;
    float l[16];
    float m = -1e30f;
    #pragma unroll
    for (int j=0;j<16;j++){ l[j] = g_logits[base + tid + 256*j]; m = fmaxf(m, l[j]); }
    #pragma unroll
    for (int o=16;o;o>>=1) m = fmaxf(m, __shfl_xor_sync(0xffffffffu,m,o));
    if (lane==0) red[warp]=m;
    __syncthreads();
    if (tid==0){ float mm=red[0]; for(int i=1;i<8;i++) mm=fmaxf(mm,red[i]); bc=mm; }
    __syncthreads();
    m = bc;
    float ex[16]; float sum=0.f;
    #pragma unroll
    for (int j=0;j<16;j++){ ex[j]=__expf(l[j]-m); sum+=ex[j]; }
    sum = warp_sum(sum);
    if (lane==0) red[warp]=sum;
    __syncthreads();
    if (tid==0){ float ss=0.f; for(int i=0;i<8;i++) ss+=red[i]; bc=ss; }
    __syncthreads();
    float inv = 1.f/bc;
    float ps=0.f;
    #pragma unroll
    for (int j=0;j<16;j++){
        int s = tid+256*j;
        float prob = ex[j]*inv;
        float2 u = gu2[base+s];
        float g0 = -__logf(-__logf(u.x+1e-20f)+1e-20f);
        float g1 = -__logf(-__logf(u.y+1e-20f)+1e-20f);
        float A = (l[j]+g1 > g0) ? 1.f : 0.f;
        float pm = A*prob;
        g_A[base+s]=A; g_pm[base+s]=pm; ps+=pm;
    }
    ps = warp_sum(ps);
    if (lane==0) red[warp]=ps;
    __syncthreads();
    if (tid==0){ float ss=0.f; for(int i=0;i<8;i++) ss+=red[i]; g_psum[bid]=ss; }
}

// ---------------- K2b: masks/attn = sum over heads (float4, h quartered) ----------------
__global__ void __launch_bounds__(256) k_sums(float* __restrict__ out){
    __shared__ float4 sA[4][64], sP[4][64];
    int tid = threadIdx.x;
    int t = tid>>2, q = tid&3;
    int sf4 = blockIdx.x*64 + t;         // global s-float4 index (0..8191)
    int b = sf4>>10, f = sf4&1023;
    const float4* A4 = (const float4*)g_A;
    const float4* P4 = (const float4*)g_pm;
    float4 ms = make_float4(0,0,0,0), as = make_float4(0,0,0,0);
    #pragma unroll
    for (int hh=0; hh<4; hh++){
        int h = q*4+hh;
        int off = ((b<<4)+h)*1024 + f;
        float4 av = A4[off], pv = P4[off];
        ms.x+=av.x; ms.y+=av.y; ms.z+=av.z; ms.w+=av.w;
        as.x+=pv.x; as.y+=pv.y; as.z+=pv.z; as.w+=pv.w;
    }
    if (q){ sA[q][t]=ms; sP[q][t]=as; }
    __syncthreads();
    if (q==0){
        #pragma unroll
        for (int g=1;g<4;g++){
            float4 av = sA[g][t], pv = sP[g][t];
            ms.x+=av.x; ms.y+=av.y; ms.z+=av.z; ms.w+=av.w;
            as.x+=pv.x; as.y+=pv.y; as.z+=pv.z; as.w+=pv.w;
        }
        float4* out4 = (float4*)out;
        out4[2048 + sf4] = ms;           // masks @ out[8192]
        out4[10240 + sf4] = as;          // attn  @ out[40960]
    }
}

// ---------------- K3: ctx partials (pass 2 over x) ----------------
// Thread: 8 heads (oct) x 8 e-floats (2 float4: col, col+128). pm dup-packed in
// smem, 4x LDS.128 broadcast per si (half the delivered bytes of R5); x via LDG.
__global__ void __launch_bounds__(256,2) k_ctx(const float4* __restrict__ x4){
    __shared__ __align__(16) ull sp[CHUNK][16];   // (p,p) dup, 16KB
    int tid = threadIdx.x;
    int b = blockIdx.x>>5, chunk = blockIdx.x&31;
    int s0 = chunk*CHUNK;
    #pragma unroll
    for (int i=0;i<8;i++){
        int idx = tid + 256*i;
        int h = idx>>7, si = idx&127;
        float p = g_pm[((b<<4)+h)*4096 + s0 + si];
        sp[si][h] = pk2(p,p);
    }
    __syncthreads();
    int col = tid&127, oct = tid>>7;
    ull acc[8][4];
    #pragma unroll
    for (int hp=0;hp<8;hp++){
        acc[hp][0]=0ULL; acc[hp][1]=0ULL; acc[hp][2]=0ULL; acc[hp][3]=0ULL;
    }
    #pragma unroll 2
    for (int si=0; si<CHUNK; si++){
        int row = b*4096 + s0 + si;
        float4 xa = __ldg(&x4[row*256 + col]);
        float4 xb = __ldg(&x4[row*256 + 128 + col]);
        ull xa01 = pk2(xa.x,xa.y), xa23 = pk2(xa.z,xa.w);
        ull xb01 = pk2(xb.x,xb.y), xb23 = pk2(xb.z,xb.w);
        ulonglong2 p01 = *(const ulonglong2*)&sp[si][oct*8];
        ulonglong2 p23 = *(const ulonglong2*)&sp[si][oct*8+2];
        ulonglong2 p45 = *(const ulonglong2*)&sp[si][oct*8+4];
        ulonglong2 p67 = *(const ulonglong2*)&sp[si][oct*8+6];
        ull pv[8] = {p01.x,p01.y,p23.x,p23.y,p45.x,p45.y,p67.x,p67.y};
        #pragma unroll
        for (int hp=0;hp<8;hp++){
            ffma2(acc[hp][0], pv[hp], xa01);
            ffma2(acc[hp][1], pv[hp], xa23);
            ffma2(acc[hp][2], pv[hp], xb01);
            ffma2(acc[hp][3], pv[hp], xb23);
        }
    }
    float4* p4 = (float4*)g_partial;
    #pragma unroll
    for (int hp=0;hp<8;hp++){
        int h = oct*8 + hp;
        int base = ((b*NCHUNK+chunk)*16 + h)*256;
        float2 a0 = upk(acc[hp][0]), a1 = upk(acc[hp][1]);
        float2 b0 = upk(acc[hp][2]), b1 = upk(acc[hp][3]);
        p4[base + col]       = make_float4(a0.x,a0.y,a1.x,a1.y);
        p4[base + 128 + col] = make_float4(b0.x,b0.y,b1.x,b1.y);
    }
}

// ---------------- K3r: deterministic reduction of ctx partials (float4) ----------------
__global__ void __launch_bounds__(256) k_ctxr(){
    int f4 = blockIdx.x*256 + threadIdx.x;   // 0..32767 float4 of ctx
    int b = f4>>12, rem = f4&4095;
    const float4* p4 = (const float4*)g_partial;
    float4 s = make_float4(0,0,0,0);
    #pragma unroll
    for (int c=0;c<NCHUNK;c++){
        float4 v = p4[((b*NCHUNK+c)<<12) + rem];
        s.x+=v.x; s.y+=v.y; s.z+=v.z; s.w+=v.w;
    }
    ((float4*)g_ctx)[f4] = s;
}

// ---------------- K4a: hidden = Wv·ctx + bv*psum ----------------
__global__ void __launch_bounds__(256) k_hidden(const float4* __restrict__ Wv4,
                                                const float*  __restrict__ bv){
    int lane = threadIdx.x&31, warp = threadIdx.x>>5;
    int row = blockIdx.x*8+warp;
    int h = row>>6;
    float4 w[8];
    #pragma unroll
    for (int k=0;k<8;k++) w[k] = Wv4[row*256 + lane + 32*k];
    const float4* c4 = (const float4*)g_ctx;
    float acc[8];
    #pragma unroll
    for (int b=0;b<8;b++){
        float s=0.f;
        #pragma unroll
        for (int k=0;k<8;k++){
            float4 c = c4[((b<<4)+h)*256 + lane + 32*k];
            s += w[k].x*c.x + w[k].y*c.y + w[k].z*c.z + w[k].w*c.w;
        }
        acc[b]=s;
    }
    #pragma unroll
    for (int o=16;o;o>>=1)
        #pragma unroll
        for (int b=0;b<8;b++) acc[b] += __shfl_xor_sync(0xffffffffu, acc[b], o);
    if (lane==0){
        float bvr = bv[row];
        #pragma unroll
        for (int b=0;b<8;b++) g_hidden[b*1024+row] = acc[b] + bvr*g_psum[(b<<4)+h];
    }
}

// ---------------- K4c: fused LN + act = relu(ln(hidden) @ W1^T + b1) ----------------
__global__ void __launch_bounds__(256) k_mlp1(const float4* __restrict__ W14,
                                              const float*  __restrict__ b1,
                                              const float4* __restrict__ lg4,
                                              const float4* __restrict__ lb4){
    __shared__ float4 hls[2048];   // 8 normalized rows x 1024 floats
    int tid = threadIdx.x, lane=tid&31, warp=tid>>5;
    {   // each warp LayerNorms batch row b=warp
        int b = warp;
        const float4* h4 = (const float4*)g_hidden;
        float4 v[8];
        float s = 0.f;
        #pragma unroll
        for (int k=0;k<8;k++){
            v[k] = h4[b*256 + lane + 32*k];
            s += v[k].x + v[k].y + v[k].z + v[k].w;
        }
        s = warp_sum(s);
        float mu = s * (1.f/1024.f);
        float q = 0.f;
        #pragma unroll
        for (int k=0;k<8;k++){
            float dx=v[k].x-mu, dy=v[k].y-mu, dz=v[k].z-mu, dw=v[k].w-mu;
            q += dx*dx + dy*dy + dz*dz + dw*dw;
        }
        q = warp_sum(q);
        float rstd = rsqrtf(q*(1.f/1024.f) + 1e-5f);
        #pragma unroll
        for (int k=0;k<8;k++){
            float4 g = lg4[lane+32*k], bb = lb4[lane+32*k];
            hls[b*256+lane+32*k] = make_float4(
                (v[k].x-mu)*rstd*g.x + bb.x,
                (v[k].y-mu)*rstd*g.y + bb.y,
                (v[k].z-mu)*rstd*g.z + bb.z,
                (v[k].w-mu)*rstd*g.w + bb.w);
        }
    }
    __syncthreads();
    int row = blockIdx.x*8+warp;
    float4 w[8];
    #pragma unroll
    for (int k=0;k<8;k++) w[k]=W14[row*256+lane+32*k];
    float acc[8];
    #pragma unroll
    for (int b=0;b<8;b++){
        float s=0.f;
        #pragma unroll
        for (int k=0;k<8;k++){
            float4 hv = hls[b*256 + lane + 32*k];
            s += w[k].x*hv.x + w[k].y*hv.y + w[k].z*hv.z + w[k].w*hv.w;
        }
        acc[b]=s;
    }
    #pragma unroll
    for (int o=16;o;o>>=1)
        #pragma unroll
        for (int b=0;b<8;b++) acc[b] += __shfl_xor_sync(0xffffffffu, acc[b], o);
    if (lane==0){
        float bb = b1[row];
        #pragma unroll
        for (int b=0;b<8;b++) g_act[b*4096+row] = fmaxf(acc[b]+bb, 0.f);
    }
}

// ---------------- K4d: out = act @ W2^T + b2 ----------------
__global__ void __launch_bounds__(256) k_mlp2(const float4* __restrict__ W24,
                                              const float*  __restrict__ b2,
                                              float* __restrict__ out){
    extern __shared__ float4 as4[];    // 8x4096 floats = 128KB dynamic
    int tid=threadIdx.x, lane=tid&31, warp=tid>>5;
    const float4* a4 = (const float4*)g_act;
    #pragma unroll
    for (int i=0;i<32;i++) as4[tid+256*i] = a4[tid+256*i];
    __syncthreads();
    int row = blockIdx.x*8+warp;
    float acc[8];
    #pragma unroll
    for (int b=0;b<8;b++) acc[b]=0.f;
    #pragma unroll 4
    for (int k=0;k<32;k++){
        float4 w = W24[row*1024 + lane + 32*k];
        #pragma unroll
        for (int b=0;b<8;b++){
            float4 av = as4[b*1024 + lane + 32*k];
            acc[b] += w.x*av.x + w.y*av.y + w.z*av.z + w.w*av.w;
        }
    }
    #pragma unroll
    for (int o=16;o;o>>=1)
        #pragma unroll
        for (int b=0;b<8;b++) acc[b] += __shfl_xor_sync(0xffffffffu, acc[b], o);
    if (lane==0){
        float bb = b2[row];
        #pragma unroll
        for (int b=0;b<8;b++) out[b*1024+row] = acc[b] + bb;
    }
}

extern "C" void kernel_launch(void* const* d_in, const int* in_sizes, int n_in,
                              void* d_out, int out_size){
    const float* x     = (const float*)d_in[0];
    const float* gu    = (const float*)d_in[1];
    const float* query = (const float*)d_in[2];
    const float* Wq    = (const float*)d_in[3];
    const float* bq    = (const float*)d_in[4];
    const float* Wk    = (const float*)d_in[5];
    const float* bk    = (const float*)d_in[6];
    const float* Wv    = (const float*)d_in[7];
    const float* bv    = (const float*)d_in[8];
    const float* ln_g  = (const float*)d_in[9];
    const float* ln_b  = (const float*)d_in[10];
    const float* W1    = (const float*)d_in[11];
    const float* b1    = (const float*)d_in[12];
    const float* W2    = (const float*)d_in[13];
    const float* b2    = (const float*)d_in[14];
    float* out = (float*)d_out;

    cudaFuncSetAttribute(k_mlp2, cudaFuncAttributeMaxDynamicSharedMemorySize, 131072);

    k_qvec   <<<128,256>>>((const float4*)Wq, (const float4*)query, bq);   // 1
    k_wqk    <<<128,256>>>((const float4*)Wk, bk);                          // 2
    k_dummy  <<<1,32>>>();                                                  // 3
    k_logits <<<1024,256>>>((const float4*)x);                              // 4 (profiled)
    k_softmax<<<128,256>>>((const float2*)gu);                              // 5
    k_sums   <<<128,256>>>(out);                                            // 6
    k_ctx    <<<256,256>>>((const float4*)x);                               // 7
    k_ctxr   <<<128,256>>>();                                               // 8
    k_hidden <<<128,256>>>((const float4*)Wv, bv);                          // 9
    k_mlp1   <<<512,256>>>((const float4*)W1, b1,
                           (const float4*)ln_g, (const float4*)ln_b);       // 10
    k_mlp2   <<<128,256,131072>>>((const float4*)W2, b2, out);              // 11
}

// round 7
// speedup vs baseline: 1.1101x; 1.1101x over previous
#include <cuda_runtime.h>
#include <math.h>

typedef unsigned long long ull;

// Problem constants
#define NB 8
#define SQ 4096
#define EE 1024
#define HH 16
#define NCHUNK 32
#define CHUNK 128

// Scratch (static device globals -- allocation-free per harness rules)
__device__ float g_wqk[HH*EE];
__device__ float g_c[HH];
__device__ float g_logits[NB*HH*SQ];
__device__ float g_pm[NB*HH*SQ];
__device__ float g_A[NB*HH*SQ];
__device__ float g_psum[NB*HH];
__device__ float g_partial[NB*NCHUNK*HH*EE];   // 16.8 MB partial ctx
__device__ float g_ctx[NB*HH*EE];
__device__ float g_hidden[NB*EE];
__device__ float g_act[NB*4*EE];

__device__ __forceinline__ float warp_sum(float v){
    #pragma unroll
    for (int o=16;o;o>>=1) v += __shfl_xor_sync(0xffffffffu, v, o);
    return v;
}

// packed f32x2 helpers
__device__ __forceinline__ void ffma2(ull &d, ull a, ull b){
    asm("fma.rn.f32x2 %0, %1, %2, %0;" : "+l"(d) : "l"(a), "l"(b));
}
__device__ __forceinline__ ull fadd2(ull a, ull b){
    ull d; asm("add.rn.f32x2 %0, %1, %2;" : "=l"(d) : "l"(a), "l"(b)); return d;
}
__device__ __forceinline__ ull pk2(float x, float y){
    float2 t = make_float2(x,y); return *(ull*)&t;
}
__device__ __forceinline__ float2 upk(ull v){ return *(float2*)&v; }

__device__ __forceinline__ void cpa16(void* s, const void* g){
    unsigned sa = (unsigned)__cvta_generic_to_shared(s);
    asm volatile("cp.async.cg.shared.global [%0],[%1],16;"::"r"(sa),"l"(g));
}

__global__ void k_dummy(){}

// ---------------- K0: fused q projection + w_qk fold (per-head block) ----------------
__global__ void __launch_bounds__(256) k_wqkf(const float4* __restrict__ Wq4,
                                              const float4* __restrict__ q4,
                                              const float*  __restrict__ bq,
                                              const float4* __restrict__ Wk4,
                                              const float*  __restrict__ bk){
    __shared__ float qv[64];
    int h = blockIdx.x, tid = threadIdx.x;
    {   // 64 rows x 4 threads each
        int r = tid>>2, c4 = tid&3;
        int row = h*64 + r;
        float acc = 0.f;
        #pragma unroll 8
        for (int j=0;j<64;j++){
            float4 w = Wq4[row*256 + c4*64 + j];
            float4 q = q4[c4*64 + j];
            acc += w.x*q.x + w.y*q.y + w.z*q.z + w.w*q.w;
        }
        acc += __shfl_xor_sync(0xffffffffu, acc, 1);
        acc += __shfl_xor_sync(0xffffffffu, acc, 2);
        if (c4==0) qv[r] = acc + bq[row];
    }
    __syncthreads();
    float4 acc = make_float4(0.f,0.f,0.f,0.f);
    #pragma unroll 8
    for (int d=0; d<64; d++){
        float w = qv[d];
        float4 kk = Wk4[(h*64+d)*256 + tid];
        acc.x += w*kk.x; acc.y += w*kk.y; acc.z += w*kk.z; acc.w += w*kk.w;
    }
    acc.x*=0.125f; acc.y*=0.125f; acc.z*=0.125f; acc.w*=0.125f;
    ((float4*)g_wqk)[h*256+tid] = acc;
    if (tid==0){
        float c=0.f;
        for (int d=0;d<64;d++) c += qv[d]*bk[h*64+d];
        g_c[h] = 0.125f*c;
    }
}

// ---------------- K1: logits = w_qk·x + c ----------------
// 8 warps, warp = 128-float e-slice. lane = hg*8+ep: hg owns 4 heads, ep spans
// 8 float4 positions. Weights 32 ull in regs. 4-row tiles double-buffered via
// cp.async. Deferred 4-shfl fold per row, off the load path.
__global__ void __launch_bounds__(256,2) k_logits(const float4* __restrict__ x4){
    __shared__ float4 sx[2][1024];     // 2 x 16KB: 4 rows x 1024 floats
    __shared__ float  sred[4][16][9];
    int tid = threadIdx.x, lane = tid&31, warp = tid>>5;
    int hg = lane>>3, ep = lane&7;
    ull wA[4][4], wB[4][4];
    {
        const float4* wq4 = (const float4*)g_wqk;
        #pragma unroll
        for (int k=0;k<4;k++){
            int F = warp*32 + k*8 + ep;
            #pragma unroll
            for (int hp=0;hp<4;hp++){
                float4 wv = wq4[(hg*4+hp)*256 + F];
                wA[k][hp] = pk2(wv.x,wv.y);
                wB[k][hp] = pk2(wv.z,wv.w);
            }
        }
    }
    int rowbase = blockIdx.x*32, b = rowbase>>12;
    bool hi4 = (lane&4)!=0, hi2 = (lane&2)!=0;

    #pragma unroll
    for (int i=0;i<4;i++) cpa16(&sx[0][i*256+tid], &x4[(rowbase+i)*256 + tid]);
    asm volatile("cp.async.commit_group;");

    for (int t=0;t<8;t++){
        if (t<7){
            int rb1 = rowbase + (t+1)*4;
            #pragma unroll
            for (int i=0;i<4;i++) cpa16(&sx[(t+1)&1][i*256+tid], &x4[(rb1+i)*256 + tid]);
            asm volatile("cp.async.commit_group;");
            asm volatile("cp.async.wait_group 1;");
        } else {
            asm volatile("cp.async.wait_group 0;");
        }
        __syncthreads();
        const ulonglong2* xs = (const ulonglong2*)sx[t&1];
        ull acc[4][4];
        #pragma unroll
        for (int r=0;r<4;r++)
            #pragma unroll
            for (int hp=0;hp<4;hp++) acc[r][hp] = 0ULL;
        #pragma unroll
        for (int r=0;r<4;r++){
            #pragma unroll
            for (int k=0;k<4;k++){
                ulonglong2 xu = xs[r*256 + warp*32 + k*8 + ep];
                #pragma unroll
                for (int hp=0;hp<4;hp++){
                    ffma2(acc[r][hp], wA[k][hp], xu.x);
                    ffma2(acc[r][hp], wB[k][hp], xu.y);
                }
            }
        }
        // fold over the 8-lane ep group: 4 heads -> lanes {0,1}{2,3}{4,5}{6,7}
        #pragma unroll
        for (int r=0;r<4;r++){
            ull s0 = hi4 ? acc[r][0] : acc[r][2];
            s0 = __shfl_xor_sync(0xffffffffu, s0, 4);
            ull a0 = fadd2(hi4 ? acc[r][2] : acc[r][0], s0);
            ull s1 = hi4 ? acc[r][1] : acc[r][3];
            s1 = __shfl_xor_sync(0xffffffffu, s1, 4);
            ull a1 = fadd2(hi4 ? acc[r][3] : acc[r][1], s1);
            ull s2 = hi2 ? a0 : a1;
            s2 = __shfl_xor_sync(0xffffffffu, s2, 2);
            ull aa = fadd2(hi2 ? a1 : a0, s2);
            aa = fadd2(aa, __shfl_xor_sync(0xffffffffu, aa, 1));
            float2 f = upk(aa);
            if ((ep&1)==0) sred[r][hg*4 + (ep>>1)][warp] = f.x + f.y;
        }
        __syncthreads();
        if (tid < 64){
            int r = tid&3, h = tid>>2;
            float s = g_c[h];
            #pragma unroll
            for (int w2=0;w2<8;w2++) s += sred[r][h][w2];
            int srow = (rowbase&4095) + t*4 + r;
            g_logits[((b<<4)+h)*4096 + srow] = s;
        }
    }
}

// ---------------- K2: softmax over S + gumbel hard mask, per (b,h) ----------------
__global__ void __launch_bounds__(256) k_softmax(const float2* __restrict__ gu2){
    __shared__ float red[8];
    __shared__ float bc;
    int bid = blockIdx.x;                 // b*16+h
    int tid = threadIdx.x, lane = tid&31, warp = tid>>5;
    int base = bid*4096;
    float l[16];
    float m = -1e30f;
    #pragma unroll
    for (int j=0;j<16;j++){ l[j] = g_logits[base + tid + 256*j]; m = fmaxf(m, l[j]); }
    #pragma unroll
    for (int o=16;o;o>>=1) m = fmaxf(m, __shfl_xor_sync(0xffffffffu,m,o));
    if (lane==0) red[warp]=m;
    __syncthreads();
    if (tid==0){ float mm=red[0]; for(int i=1;i<8;i++) mm=fmaxf(mm,red[i]); bc=mm; }
    __syncthreads();
    m = bc;
    float ex[16]; float sum=0.f;
    #pragma unroll
    for (int j=0;j<16;j++){ ex[j]=__expf(l[j]-m); sum+=ex[j]; }
    sum = warp_sum(sum);
    if (lane==0) red[warp]=sum;
    __syncthreads();
    if (tid==0){ float ss=0.f; for(int i=0;i<8;i++) ss+=red[i]; bc=ss; }
    __syncthreads();
    float inv = 1.f/bc;
    float ps=0.f;
    #pragma unroll
    for (int j=0;j<16;j++){
        int s = tid+256*j;
        float prob = ex[j]*inv;
        float2 u = gu2[base+s];
        float g0 = -__logf(-__logf(u.x+1e-20f)+1e-20f);
        float g1 = -__logf(-__logf(u.y+1e-20f)+1e-20f);
        float A = (l[j]+g1 > g0) ? 1.f : 0.f;
        float pm = A*prob;
        g_A[base+s]=A; g_pm[base+s]=pm; ps+=pm;
    }
    ps = warp_sum(ps);
    if (lane==0) red[warp]=ps;
    __syncthreads();
    if (tid==0){ float ss=0.f; for(int i=0;i<8;i++) ss+=red[i]; g_psum[bid]=ss; }
}

// ---------------- K3: ctx partials (pass 2 over x) + fused masks/attn sums ----------------
__global__ void __launch_bounds__(256,2) k_ctx(const float4* __restrict__ x4,
                                               float* __restrict__ out){
    __shared__ __align__(16) ull sp[CHUNK][16];   // (p,p) dup, 16KB
    int tid = threadIdx.x;
    int b = blockIdx.x>>5, chunk = blockIdx.x&31;
    int s0 = chunk*CHUNK;
    #pragma unroll
    for (int i=0;i<8;i++){
        int idx = tid + 256*i;
        int h = idx>>7, si = idx&127;
        float p = g_pm[((b<<4)+h)*4096 + s0 + si];
        sp[si][h] = pk2(p,p);
    }
    // fused k_sums: masks/attn head-sums for this (b, s-chunk)
    if (tid < 128){
        int s = s0 + tid;
        float ms=0.f, as=0.f;
        #pragma unroll
        for (int h=0;h<16;h++){
            int off = ((b<<4)+h)*4096 + s;
            ms += g_A[off];
            as += g_pm[off];
        }
        out[8192 + b*4096 + s] = ms;
        out[8192 + 32768 + b*4096 + s] = as;
    }
    __syncthreads();
    int col = tid&127, oct = tid>>7;
    ull acc[8][4];
    #pragma unroll
    for (int hp=0;hp<8;hp++){
        acc[hp][0]=0ULL; acc[hp][1]=0ULL; acc[hp][2]=0ULL; acc[hp][3]=0ULL;
    }
    #pragma unroll 4
    for (int si=0; si<CHUNK; si++){
        int row = b*4096 + s0 + si;
        float4 xa = __ldg(&x4[row*256 + col]);
        float4 xb = __ldg(&x4[row*256 + 128 + col]);
        ull xa01 = pk2(xa.x,xa.y), xa23 = pk2(xa.z,xa.w);
        ull xb01 = pk2(xb.x,xb.y), xb23 = pk2(xb.z,xb.w);
        ulonglong2 p01 = *(const ulonglong2*)&sp[si][oct*8];
        ulonglong2 p23 = *(const ulonglong2*)&sp[si][oct*8+2];
        ulonglong2 p45 = *(const ulonglong2*)&sp[si][oct*8+4];
        ulonglong2 p67 = *(const ulonglong2*)&sp[si][oct*8+6];
        ull pv[8] = {p01.x,p01.y,p23.x,p23.y,p45.x,p45.y,p67.x,p67.y};
        #pragma unroll
        for (int hp=0;hp<8;hp++){
            ffma2(acc[hp][0], pv[hp], xa01);
            ffma2(acc[hp][1], pv[hp], xa23);
            ffma2(acc[hp][2], pv[hp], xb01);
            ffma2(acc[hp][3], pv[hp], xb23);
        }
    }
    float4* p4 = (float4*)g_partial;
    #pragma unroll
    for (int hp=0;hp<8;hp++){
        int h = oct*8 + hp;
        int base = ((b*NCHUNK+chunk)*16 + h)*256;
        float2 a0 = upk(acc[hp][0]), a1 = upk(acc[hp][1]);
        float2 b0 = upk(acc[hp][2]), b1 = upk(acc[hp][3]);
        p4[base + col]       = make_float4(a0.x,a0.y,a1.x,a1.y);
        p4[base + 128 + col] = make_float4(b0.x,b0.y,b1.x,b1.y);
    }
}

// ---------------- K3r: deterministic reduction of ctx partials (float4) ----------------
__global__ void __launch_bounds__(256) k_ctxr(){
    int f4 = blockIdx.x*256 + threadIdx.x;   // 0..32767 float4 of ctx
    int b = f4>>12, rem = f4&4095;
    const float4* p4 = (const float4*)g_partial;
    float4 s = make_float4(0,0,0,0);
    #pragma unroll
    for (int c=0;c<NCHUNK;c++){
        float4 v = p4[((b*NCHUNK+c)<<12) + rem];
        s.x+=v.x; s.y+=v.y; s.z+=v.z; s.w+=v.w;
    }
    ((float4*)g_ctx)[f4] = s;
}

// ---------------- K4a: hidden = Wv·ctx + bv*psum ----------------
__global__ void __launch_bounds__(256) k_hidden(const float4* __restrict__ Wv4,
                                                const float*  __restrict__ bv){
    int lane = threadIdx.x&31, warp = threadIdx.x>>5;
    int row = blockIdx.x*8+warp;
    int h = row>>6;
    float4 w[8];
    #pragma unroll
    for (int k=0;k<8;k++) w[k] = Wv4[row*256 + lane + 32*k];
    const float4* c4 = (const float4*)g_ctx;
    float acc[8];
    #pragma unroll
    for (int b=0;b<8;b++){
        float s=0.f;
        #pragma unroll
        for (int k=0;k<8;k++){
            float4 c = c4[((b<<4)+h)*256 + lane + 32*k];
            s += w[k].x*c.x + w[k].y*c.y + w[k].z*c.z + w[k].w*c.w;
        }
        acc[b]=s;
    }
    #pragma unroll
    for (int o=16;o;o>>=1)
        #pragma unroll
        for (int b=0;b<8;b++) acc[b] += __shfl_xor_sync(0xffffffffu, acc[b], o);
    if (lane==0){
        float bvr = bv[row];
        #pragma unroll
        for (int b=0;b<8;b++) g_hidden[b*1024+row] = acc[b] + bvr*g_psum[(b<<4)+h];
    }
}

// ---------------- K4c: fused LN + act = relu(ln(hidden) @ W1^T + b1) ----------------
__global__ void __launch_bounds__(256) k_mlp1(const float4* __restrict__ W14,
                                              const float*  __restrict__ b1,
                                              const float4* __restrict__ lg4,
                                              const float4* __restrict__ lb4){
    __shared__ float4 hls[2048];   // 8 normalized rows x 1024 floats
    int tid = threadIdx.x, lane=tid&31, warp=tid>>5;
    {   // each warp LayerNorms batch row b=warp
        int b = warp;
        const float4* h4 = (const float4*)g_hidden;
        float4 v[8];
        float s = 0.f;
        #pragma unroll
        for (int k=0;k<8;k++){
            v[k] = h4[b*256 + lane + 32*k];
            s += v[k].x + v[k].y + v[k].z + v[k].w;
        }
        s = warp_sum(s);
        float mu = s * (1.f/1024.f);
        float q = 0.f;
        #pragma unroll
        for (int k=0;k<8;k++){
            float dx=v[k].x-mu, dy=v[k].y-mu, dz=v[k].z-mu, dw=v[k].w-mu;
            q += dx*dx + dy*dy + dz*dz + dw*dw;
        }
        q = warp_sum(q);
        float rstd = rsqrtf(q*(1.f/1024.f) + 1e-5f);
        #pragma unroll
        for (int k=0;k<8;k++){
            float4 g = lg4[lane+32*k], bb = lb4[lane+32*k];
            hls[b*256+lane+32*k] = make_float4(
                (v[k].x-mu)*rstd*g.x + bb.x,
                (v[k].y-mu)*rstd*g.y + bb.y,
                (v[k].z-mu)*rstd*g.z + bb.z,
                (v[k].w-mu)*rstd*g.w + bb.w);
        }
    }
    __syncthreads();
    int row = blockIdx.x*8+warp;
    float4 w[8];
    #pragma unroll
    for (int k=0;k<8;k++) w[k]=W14[row*256+lane+32*k];
    float acc[8];
    #pragma unroll
    for (int b=0;b<8;b++){
        float s=0.f;
        #pragma unroll
        for (int k=0;k<8;k++){
            float4 hv = hls[b*256 + lane + 32*k];
            s += w[k].x*hv.x + w[k].y*hv.y + w[k].z*hv.z + w[k].w*hv.w;
        }
        acc[b]=s;
    }
    #pragma unroll
    for (int o=16;o;o>>=1)
        #pragma unroll
        for (int b=0;b<8;b++) acc[b] += __shfl_xor_sync(0xffffffffu, acc[b], o);
    if (lane==0){
        float bb = b1[row];
        #pragma unroll
        for (int b=0;b<8;b++) g_act[b*4096+row] = fmaxf(acc[b]+bb, 0.f);
    }
}

// ---------------- K4d: out = act @ W2^T + b2 ----------------
__global__ void __launch_bounds__(256) k_mlp2(const float4* __restrict__ W24,
                                              const float*  __restrict__ b2,
                                              float* __restrict__ out){
    extern __shared__ float4 as4[];    // 8x4096 floats = 128KB dynamic
    int tid=threadIdx.x, lane=tid&31, warp=tid>>5;
    const float4* a4 = (const float4*)g_act;
    #pragma unroll
    for (int i=0;i<32;i++) as4[tid+256*i] = a4[tid+256*i];
    __syncthreads();
    int row = blockIdx.x*8+warp;
    float acc[8];
    #pragma unroll
    for (int b=0;b<8;b++) acc[b]=0.f;
    #pragma unroll 4
    for (int k=0;k<32;k++){
        float4 w = W24[row*1024 + lane + 32*k];
        #pragma unroll
        for (int b=0;b<8;b++){
            float4 av = as4[b*1024 + lane + 32*k];
            acc[b] += w.x*av.x + w.y*av.y + w.z*av.z + w.w*av.w;
        }
    }
    #pragma unroll
    for (int o=16;o;o>>=1)
        #pragma unroll
        for (int b=0;b<8;b++) acc[b] += __shfl_xor_sync(0xffffffffu, acc[b], o);
    if (lane==0){
        float bb = b2[row];
        #pragma unroll
        for (int b=0;b<8;b++) out[b*1024+row] = acc[b] + bb;
    }
}

extern "C" void kernel_launch(void* const* d_in, const int* in_sizes, int n_in,
                              void* d_out, int out_size){
    const float* x     = (const float*)d_in[0];
    const float* gu    = (const float*)d_in[1];
    const float* query = (const float*)d_in[2];
    const float* Wq    = (const float*)d_in[3];
    const float* bq    = (const float*)d_in[4];
    const float* Wk    = (const float*)d_in[5];
    const float* bk    = (const float*)d_in[6];
    const float* Wv    = (const float*)d_in[7];
    const float* bv    = (const float*)d_in[8];
    const float* ln_g  = (const float*)d_in[9];
    const float* ln_b  = (const float*)d_in[10];
    const float* W1    = (const float*)d_in[11];
    const float* b1    = (const float*)d_in[12];
    const float* W2    = (const float*)d_in[13];
    const float* b2    = (const float*)d_in[14];
    float* out = (float*)d_out;

    cudaFuncSetAttribute(k_mlp2, cudaFuncAttributeMaxDynamicSharedMemorySize, 131072);

    k_wqkf   <<<16,256>>>((const float4*)Wq, (const float4*)query, bq,
                          (const float4*)Wk, bk);                           // 1
    k_dummy  <<<1,32>>>();                                                  // 2
    k_dummy  <<<1,32>>>();                                                  // 3
    k_logits <<<1024,256>>>((const float4*)x);                              // 4 (profiled)
    k_softmax<<<128,256>>>((const float2*)gu);                              // 5
    k_ctx    <<<256,256>>>((const float4*)x, out);                          // 6
    k_ctxr   <<<128,256>>>();                                               // 7
    k_hidden <<<128,256>>>((const float4*)Wv, bv);                          // 8
    k_mlp1   <<<512,256>>>((const float4*)W1, b1,
                           (const float4*)ln_g, (const float4*)ln_b);       // 9
    k_mlp2   <<<128,256,131072>>>((const float4*)W2, b2, out);              // 10
}

// round 8
// speedup vs baseline: 1.1817x; 1.0644x over previous
#include <cuda_runtime.h>
#include <math.h>

typedef unsigned long long ull;

// Problem constants
#define NB 8
#define SQ 4096
#define EE 1024
#define HH 16
#define NCHUNK 32
#define CHUNK 128

// Scratch (static device globals -- allocation-free per harness rules)
__device__ float g_wqk[HH*EE];
__device__ float g_c[HH];
__device__ float g_logits[NB*HH*SQ];
__device__ float g_pm[NB*HH*SQ];
__device__ float g_A[NB*HH*SQ];
__device__ float g_psum[NB*HH];
__device__ float g_partial[NB*NCHUNK*HH*EE];   // 16.8 MB partial ctx
__device__ float g_ctx[NB*HH*EE];
__device__ float g_hidden[NB*EE];
__device__ float g_act[NB*4*EE];

__device__ __forceinline__ float warp_sum(float v){
    #pragma unroll
    for (int o=16;o;o>>=1) v += __shfl_xor_sync(0xffffffffu, v, o);
    return v;
}

// packed f32x2 helpers
__device__ __forceinline__ void ffma2(ull &d, ull a, ull b){
    asm("fma.rn.f32x2 %0, %1, %2, %0;" : "+l"(d) : "l"(a), "l"(b));
}
__device__ __forceinline__ ull fadd2(ull a, ull b){
    ull d; asm("add.rn.f32x2 %0, %1, %2;" : "=l"(d) : "l"(a), "l"(b)); return d;
}
__device__ __forceinline__ ull pk2(float x, float y){
    float2 t = make_float2(x,y); return *(ull*)&t;
}
__device__ __forceinline__ float2 upk(ull v){ return *(float2*)&v; }

__device__ __forceinline__ void cpa16(void* s, const void* g){
    unsigned sa = (unsigned)__cvta_generic_to_shared(s);
    asm volatile("cp.async.cg.shared.global [%0],[%1],16;"::"r"(sa),"l"(g));
}

// ---------------- K0: q projection (redundant per block) + w_qk e-slice ----------------
// grid 128 = 16 h x 8 e-slices.
__global__ void __launch_bounds__(256) k_wqkf(const float4* __restrict__ Wq4,
                                              const float4* __restrict__ q4,
                                              const float*  __restrict__ bq,
                                              const float*  __restrict__ Wk,
                                              const float*  __restrict__ bk){
    __shared__ float qv[64];
    __shared__ float acc2[128];
    int h = blockIdx.x>>3, es = blockIdx.x&7;
    int tid = threadIdx.x;
    {   // 64 rows x 4 threads each (redundant across es, parallel across chip)
        int r = tid>>2, c4 = tid&3;
        int row = h*64 + r;
        float acc = 0.f;
        #pragma unroll 8
        for (int j=0;j<64;j++){
            float4 w = Wq4[row*256 + c4*64 + j];
            float4 q = q4[c4*64 + j];
            acc += w.x*q.x + w.y*q.y + w.z*q.z + w.w*q.w;
        }
        acc += __shfl_xor_sync(0xffffffffu, acc, 1);
        acc += __shfl_xor_sync(0xffffffffu, acc, 2);
        if (c4==0) qv[r] = acc + bq[row];
    }
    __syncthreads();
    {
        int c = tid&127, dh = tid>>7;
        float acc = 0.f;
        #pragma unroll 8
        for (int j=0;j<32;j++){
            int d = dh*32 + j;
            acc += qv[d] * Wk[(h*64+d)*1024 + es*128 + c];
        }
        if (dh==1) acc2[c] = acc;
        __syncthreads();
        if (dh==0)
            g_wqk[h*1024 + es*128 + c] = 0.125f*(acc + acc2[c]);
    }
    if (es==0 && tid==0){
        float c=0.f;
        for (int d=0;d<64;d++) c += qv[d]*bk[h*64+d];
        g_c[h] = 0.125f*c;
    }
}

// ---------------- K1: logits = w_qk·x + c ----------------
// Warp-private double-buffered pipeline: each warp owns its 128-float e-slice.
// Zero block barriers in the mainloop (syncwarp only). Per-warp fold results
// land in sred; single final barrier + coalesced epilogue.
__global__ void __launch_bounds__(256,2) k_logits(const float4* __restrict__ x4){
    __shared__ float4 sxw[8][2][4][32];   // 32KB, warp-private double buffers
    __shared__ float  sred[8][32][16];    // 16KB [warp][row][head]
    int tid = threadIdx.x, lane = tid&31, warp = tid>>5;
    int hg = lane>>3, ep = lane&7;
    ull wA[4][4], wB[4][4];
    {
        const float4* wq4 = (const float4*)g_wqk;
        #pragma unroll
        for (int k=0;k<4;k++){
            int F = warp*32 + k*8 + ep;
            #pragma unroll
            for (int hp=0;hp<4;hp++){
                float4 wv = wq4[(hg*4+hp)*256 + F];
                wA[k][hp] = pk2(wv.x,wv.y);
                wB[k][hp] = pk2(wv.z,wv.w);
            }
        }
    }
    int rowbase = blockIdx.x*32, b = rowbase>>12;
    bool hi4 = (lane&4)!=0, hi2 = (lane&2)!=0;

    #pragma unroll
    for (int r=0;r<4;r++)
        cpa16(&sxw[warp][0][r][lane], &x4[(rowbase+r)*256 + warp*32 + lane]);
    asm volatile("cp.async.commit_group;");

    for (int t=0;t<8;t++){
        if (t<7){
            int rb1 = rowbase + (t+1)*4;
            #pragma unroll
            for (int r=0;r<4;r++)
                cpa16(&sxw[warp][(t+1)&1][r][lane], &x4[(rb1+r)*256 + warp*32 + lane]);
            asm volatile("cp.async.commit_group;");
            asm volatile("cp.async.wait_group 1;");
        } else {
            asm volatile("cp.async.wait_group 0;");
        }
        __syncwarp();
        const ulonglong2* xs = (const ulonglong2*)&sxw[warp][t&1][0][0] + ep;
        ull acc[4][4];
        #pragma unroll
        for (int r=0;r<4;r++)
            #pragma unroll
            for (int hp=0;hp<4;hp++) acc[r][hp] = 0ULL;
        #pragma unroll
        for (int r=0;r<4;r++){
            #pragma unroll
            for (int k=0;k<4;k++){
                ulonglong2 xu = xs[r*32 + k*8];
                #pragma unroll
                for (int hp=0;hp<4;hp++){
                    ffma2(acc[r][hp], wA[k][hp], xu.x);
                    ffma2(acc[r][hp], wB[k][hp], xu.y);
                }
            }
        }
        #pragma unroll
        for (int r=0;r<4;r++){
            ull s0 = hi4 ? acc[r][0] : acc[r][2];
            s0 = __shfl_xor_sync(0xffffffffu, s0, 4);
            ull a0 = fadd2(hi4 ? acc[r][2] : acc[r][0], s0);
            ull s1 = hi4 ? acc[r][1] : acc[r][3];
            s1 = __shfl_xor_sync(0xffffffffu, s1, 4);
            ull a1 = fadd2(hi4 ? acc[r][3] : acc[r][1], s1);
            ull s2 = hi2 ? a0 : a1;
            s2 = __shfl_xor_sync(0xffffffffu, s2, 2);
            ull aa = fadd2(hi2 ? a1 : a0, s2);
            aa = fadd2(aa, __shfl_xor_sync(0xffffffffu, aa, 1));
            float2 f = upk(aa);
            if ((ep&1)==0) sred[warp][t*4+r][hg*4 + (ep>>1)] = f.x + f.y;
        }
        __syncwarp();
    }
    __syncthreads();
    {
        int h = tid>>5, row = tid&31;
        int sbase = (rowbase&4095) + row;
        #pragma unroll
        for (int hh=0; hh<2; hh++){
            int hc = h + hh*8;
            float s = g_c[hc];
            #pragma unroll
            for (int w=0;w<8;w++) s += sred[w][row][hc];
            g_logits[((b<<4)+hc)*4096 + sbase] = s;
        }
    }
}

// ---------------- K2: softmax over S + gumbel hard mask, per (b,h) ----------------
__global__ void __launch_bounds__(256) k_softmax(const float2* __restrict__ gu2){
    __shared__ float red[8];
    __shared__ float bc;
    int bid = blockIdx.x;                 // b*16+h
    int tid = threadIdx.x, lane = tid&31, warp = tid>>5;
    int base = bid*4096;
    float l[16];
    float m = -1e30f;
    #pragma unroll
    for (int j=0;j<16;j++){ l[j] = g_logits[base + tid + 256*j]; m = fmaxf(m, l[j]); }
    #pragma unroll
    for (int o=16;o;o>>=1) m = fmaxf(m, __shfl_xor_sync(0xffffffffu,m,o));
    if (lane==0) red[warp]=m;
    __syncthreads();
    if (tid==0){ float mm=red[0]; for(int i=1;i<8;i++) mm=fmaxf(mm,red[i]); bc=mm; }
    __syncthreads();
    m = bc;
    float ex[16]; float sum=0.f;
    #pragma unroll
    for (int j=0;j<16;j++){ ex[j]=__expf(l[j]-m); sum+=ex[j]; }
    sum = warp_sum(sum);
    if (lane==0) red[warp]=sum;
    __syncthreads();
    if (tid==0){ float ss=0.f; for(int i=0;i<8;i++) ss+=red[i]; bc=ss; }
    __syncthreads();
    float inv = 1.f/bc;
    float ps=0.f;
    #pragma unroll
    for (int j=0;j<16;j++){
        int s = tid+256*j;
        float prob = ex[j]*inv;
        float2 u = gu2[base+s];
        float g0 = -__logf(-__logf(u.x+1e-20f)+1e-20f);
        float g1 = -__logf(-__logf(u.y+1e-20f)+1e-20f);
        float A = (l[j]+g1 > g0) ? 1.f : 0.f;
        float pm = A*prob;
        g_A[base+s]=A; g_pm[base+s]=pm; ps+=pm;
    }
    ps = warp_sum(ps);
    if (lane==0) red[warp]=ps;
    __syncthreads();
    if (tid==0){ float ss=0.f; for(int i=0;i<8;i++) ss+=red[i]; g_psum[bid]=ss; }
}

// ---------------- K3: ctx partials (pass 2 over x) + fused masks/attn sums ----------------
__global__ void __launch_bounds__(256,2) k_ctx(const float4* __restrict__ x4,
                                               float* __restrict__ out){
    __shared__ __align__(16) ull sp[CHUNK][16];   // (p,p) dup, 16KB
    int tid = threadIdx.x;
    int b = blockIdx.x>>5, chunk = blockIdx.x&31;
    int s0 = chunk*CHUNK;
    #pragma unroll
    for (int i=0;i<8;i++){
        int idx = tid + 256*i;
        int h = idx>>7, si = idx&127;
        float p = g_pm[((b<<4)+h)*4096 + s0 + si];
        sp[si][h] = pk2(p,p);
    }
    // fused k_sums: masks/attn head-sums for this (b, s-chunk)
    if (tid < 128){
        int s = s0 + tid;
        float ms=0.f, as=0.f;
        #pragma unroll
        for (int h=0;h<16;h++){
            int off = ((b<<4)+h)*4096 + s;
            ms += g_A[off];
            as += g_pm[off];
        }
        out[8192 + b*4096 + s] = ms;
        out[8192 + 32768 + b*4096 + s] = as;
    }
    __syncthreads();
    int col = tid&127, oct = tid>>7;
    ull acc[8][4];
    #pragma unroll
    for (int hp=0;hp<8;hp++){
        acc[hp][0]=0ULL; acc[hp][1]=0ULL; acc[hp][2]=0ULL; acc[hp][3]=0ULL;
    }
    #pragma unroll 8
    for (int si=0; si<CHUNK; si++){
        int row = b*4096 + s0 + si;
        float4 xa = __ldg(&x4[row*256 + col]);
        float4 xb = __ldg(&x4[row*256 + 128 + col]);
        ull xa01 = pk2(xa.x,xa.y), xa23 = pk2(xa.z,xa.w);
        ull xb01 = pk2(xb.x,xb.y), xb23 = pk2(xb.z,xb.w);
        ulonglong2 p01 = *(const ulonglong2*)&sp[si][oct*8];
        ulonglong2 p23 = *(const ulonglong2*)&sp[si][oct*8+2];
        ulonglong2 p45 = *(const ulonglong2*)&sp[si][oct*8+4];
        ulonglong2 p67 = *(const ulonglong2*)&sp[si][oct*8+6];
        ull pv[8] = {p01.x,p01.y,p23.x,p23.y,p45.x,p45.y,p67.x,p67.y};
        #pragma unroll
        for (int hp=0;hp<8;hp++){
            ffma2(acc[hp][0], pv[hp], xa01);
            ffma2(acc[hp][1], pv[hp], xa23);
            ffma2(acc[hp][2], pv[hp], xb01);
            ffma2(acc[hp][3], pv[hp], xb23);
        }
    }
    float4* p4 = (float4*)g_partial;
    #pragma unroll
    for (int hp=0;hp<8;hp++){
        int h = oct*8 + hp;
        int base = ((b*NCHUNK+chunk)*16 + h)*256;
        float2 a0 = upk(acc[hp][0]), a1 = upk(acc[hp][1]);
        float2 b0 = upk(acc[hp][2]), b1 = upk(acc[hp][3]);
        p4[base + col]       = make_float4(a0.x,a0.y,a1.x,a1.y);
        p4[base + 128 + col] = make_float4(b0.x,b0.y,b1.x,b1.y);
    }
}

// ---------------- K3r: deterministic reduction of ctx partials (float4) ----------------
__global__ void __launch_bounds__(256) k_ctxr(){
    int f4 = blockIdx.x*256 + threadIdx.x;   // 0..32767 float4 of ctx
    int b = f4>>12, rem = f4&4095;
    const float4* p4 = (const float4*)g_partial;
    float4 s = make_float4(0,0,0,0);
    #pragma unroll
    for (int c=0;c<NCHUNK;c++){
        float4 v = p4[((b*NCHUNK+c)<<12) + rem];
        s.x+=v.x; s.y+=v.y; s.z+=v.z; s.w+=v.w;
    }
    ((float4*)g_ctx)[f4] = s;
}

// ---------------- K4a: hidden = Wv·ctx + bv*psum ----------------
__global__ void __launch_bounds__(256) k_hidden(const float4* __restrict__ Wv4,
                                                const float*  __restrict__ bv){
    int lane = threadIdx.x&31, warp = threadIdx.x>>5;
    int row = blockIdx.x*8+warp;
    int h = row>>6;
    float4 w[8];
    #pragma unroll
    for (int k=0;k<8;k++) w[k] = Wv4[row*256 + lane + 32*k];
    const float4* c4 = (const float4*)g_ctx;
    float acc[8];
    #pragma unroll
    for (int b=0;b<8;b++){
        float s=0.f;
        #pragma unroll
        for (int k=0;k<8;k++){
            float4 c = c4[((b<<4)+h)*256 + lane + 32*k];
            s += w[k].x*c.x + w[k].y*c.y + w[k].z*c.z + w[k].w*c.w;
        }
        acc[b]=s;
    }
    #pragma unroll
    for (int o=16;o;o>>=1)
        #pragma unroll
        for (int b=0;b<8;b++) acc[b] += __shfl_xor_sync(0xffffffffu, acc[b], o);
    if (lane==0){
        float bvr = bv[row];
        #pragma unroll
        for (int b=0;b<8;b++) g_hidden[b*1024+row] = acc[b] + bvr*g_psum[(b<<4)+h];
    }
}

// ---------------- K4c: fused LN + act = relu(ln(hidden) @ W1^T + b1) ----------------
__global__ void __launch_bounds__(256) k_mlp1(const float4* __restrict__ W14,
                                              const float*  __restrict__ b1,
                                              const float4* __restrict__ lg4,
                                              const float4* __restrict__ lb4){
    __shared__ float4 hls[2048];   // 8 normalized rows x 1024 floats
    int tid = threadIdx.x, lane=tid&31, warp=tid>>5;
    {   // each warp LayerNorms batch row b=warp
        int b = warp;
        const float4* h4 = (const float4*)g_hidden;
        float4 v[8];
        float s = 0.f;
        #pragma unroll
        for (int k=0;k<8;k++){
            v[k] = h4[b*256 + lane + 32*k];
            s += v[k].x + v[k].y + v[k].z + v[k].w;
        }
        s = warp_sum(s);
        float mu = s * (1.f/1024.f);
        float q = 0.f;
        #pragma unroll
        for (int k=0;k<8;k++){
            float dx=v[k].x-mu, dy=v[k].y-mu, dz=v[k].z-mu, dw=v[k].w-mu;
            q += dx*dx + dy*dy + dz*dz + dw*dw;
        }
        q = warp_sum(q);
        float rstd = rsqrtf(q*(1.f/1024.f) + 1e-5f);
        #pragma unroll
        for (int k=0;k<8;k++){
            float4 g = lg4[lane+32*k], bb = lb4[lane+32*k];
            hls[b*256+lane+32*k] = make_float4(
                (v[k].x-mu)*rstd*g.x + bb.x,
                (v[k].y-mu)*rstd*g.y + bb.y,
                (v[k].z-mu)*rstd*g.z + bb.z,
                (v[k].w-mu)*rstd*g.w + bb.w);
        }
    }
    __syncthreads();
    int row = blockIdx.x*8+warp;
    float4 w[8];
    #pragma unroll
    for (int k=0;k<8;k++) w[k]=W14[row*256+lane+32*k];
    float acc[8];
    #pragma unroll
    for (int b=0;b<8;b++){
        float s=0.f;
        #pragma unroll
        for (int k=0;k<8;k++){
            float4 hv = hls[b*256 + lane + 32*k];
            s += w[k].x*hv.x + w[k].y*hv.y + w[k].z*hv.z + w[k].w*hv.w;
        }
        acc[b]=s;
    }
    #pragma unroll
    for (int o=16;o;o>>=1)
        #pragma unroll
        for (int b=0;b<8;b++) acc[b] += __shfl_xor_sync(0xffffffffu, acc[b], o);
    if (lane==0){
        float bb = b1[row];
        #pragma unroll
        for (int b=0;b<8;b++) g_act[b*4096+row] = fmaxf(acc[b]+bb, 0.f);
    }
}

// ---------------- K4d: out = act @ W2^T + b2 ----------------
__global__ void __launch_bounds__(256) k_mlp2(const float4* __restrict__ W24,
                                              const float*  __restrict__ b2,
                                              float* __restrict__ out){
    extern __shared__ float4 as4[];    // 8x4096 floats = 128KB dynamic
    int tid=threadIdx.x, lane=tid&31, warp=tid>>5;
    const float4* a4 = (const float4*)g_act;
    #pragma unroll
    for (int i=0;i<32;i++) as4[tid+256*i] = a4[tid+256*i];
    __syncthreads();
    int row = blockIdx.x*8+warp;
    float acc[8];
    #pragma unroll
    for (int b=0;b<8;b++) acc[b]=0.f;
    #pragma unroll 4
    for (int k=0;k<32;k++){
        float4 w = W24[row*1024 + lane + 32*k];
        #pragma unroll
        for (int b=0;b<8;b++){
            float4 av = as4[b*1024 + lane + 32*k];
            acc[b] += w.x*av.x + w.y*av.y + w.z*av.z + w.w*av.w;
        }
    }
    #pragma unroll
    for (int o=16;o;o>>=1)
        #pragma unroll
        for (int b=0;b<8;b++) acc[b] += __shfl_xor_sync(0xffffffffu, acc[b], o);
    if (lane==0){
        float bb = b2[row];
        #pragma unroll
        for (int b=0;b<8;b++) out[b*1024+row] = acc[b] + bb;
    }
}

extern "C" void kernel_launch(void* const* d_in, const int* in_sizes, int n_in,
                              void* d_out, int out_size){
    const float* x     = (const float*)d_in[0];
    const float* gu    = (const float*)d_in[1];
    const float* query = (const float*)d_in[2];
    const float* Wq    = (const float*)d_in[3];
    const float* bq    = (const float*)d_in[4];
    const float* Wk    = (const float*)d_in[5];
    const float* bk    = (const float*)d_in[6];
    const float* Wv    = (const float*)d_in[7];
    const float* bv    = (const float*)d_in[8];
    const float* ln_g  = (const float*)d_in[9];
    const float* ln_b  = (const float*)d_in[10];
    const float* W1    = (const float*)d_in[11];
    const float* b1    = (const float*)d_in[12];
    const float* W2    = (const float*)d_in[13];
    const float* b2    = (const float*)d_in[14];
    float* out = (float*)d_out;

    cudaFuncSetAttribute(k_mlp2, cudaFuncAttributeMaxDynamicSharedMemorySize, 131072);

    k_wqkf   <<<128,256>>>((const float4*)Wq, (const float4*)query, bq,
                           Wk, bk);                                         // 1
    k_logits <<<1024,256>>>((const float4*)x);                              // 2
    k_softmax<<<128,256>>>((const float2*)gu);                              // 3
    k_ctx    <<<256,256>>>((const float4*)x, out);                          // 4 (profiled)
    k_ctxr   <<<128,256>>>();                                               // 5
    k_hidden <<<128,256>>>((const float4*)Wv, bv);                          // 6
    k_mlp1   <<<512,256>>>((const float4*)W1, b1,
                           (const float4*)ln_g, (const float4*)ln_b);       // 7
    k_mlp2   <<<128,256,131072>>>((const float4*)W2, b2, out);              // 8
}

// round 10
// speedup vs baseline: 1.2355x; 1.0456x over previous
#include <cuda_runtime.h>
#include <math.h>

typedef unsigned long long ull;

// Problem constants
#define NB 8
#define SQ 4096
#define EE 1024
#define HH 16
#define NCHUNK 37
#define CSZ_MAX 112

// Scratch (static device globals -- allocation-free per harness rules)
__device__ float g_wqk[HH*EE];
__device__ float g_c[HH];
__device__ float g_logits[NB*HH*SQ];
__device__ float g_pm[NB*HH*SQ];
__device__ float g_A[NB*HH*SQ];
__device__ float g_psum[NB*HH];
__device__ float g_partial[NB*NCHUNK*HH*EE];   // 19.4 MB partial ctx
__device__ float g_ctx[NB*HH*EE];
__device__ float g_hidden[NB*EE];
__device__ float g_act[NB*4*EE];

__device__ __forceinline__ float warp_sum(float v){
    #pragma unroll
    for (int o=16;o;o>>=1) v += __shfl_xor_sync(0xffffffffu, v, o);
    return v;
}

// packed f32x2 helpers
__device__ __forceinline__ void ffma2(ull &d, ull a, ull b){
    asm("fma.rn.f32x2 %0, %1, %2, %0;" : "+l"(d) : "l"(a), "l"(b));
}
__device__ __forceinline__ ull fadd2(ull a, ull b){
    ull d; asm("add.rn.f32x2 %0, %1, %2;" : "=l"(d) : "l"(a), "l"(b)); return d;
}
__device__ __forceinline__ ull pk2(float x, float y){
    float2 t = make_float2(x,y); return *(ull*)&t;
}
__device__ __forceinline__ float2 upk(ull v){ return *(float2*)&v; }

__device__ __forceinline__ void cpa16(void* s, const void* g){
    unsigned sa = (unsigned)__cvta_generic_to_shared(s);
    asm volatile("cp.async.cg.shared.global [%0],[%1],16;"::"r"(sa),"l"(g));
}

// ---------------- K0: q projection (redundant per block) + w_qk e-slice ----------------
__global__ void __launch_bounds__(256) k_wqkf(const float4* __restrict__ Wq4,
                                              const float4* __restrict__ q4,
                                              const float*  __restrict__ bq,
                                              const float*  __restrict__ Wk,
                                              const float*  __restrict__ bk){
    __shared__ float qv[64];
    __shared__ float acc2[128];
    int h = blockIdx.x>>3, es = blockIdx.x&7;
    int tid = threadIdx.x;
    {
        int r = tid>>2, c4 = tid&3;
        int row = h*64 + r;
        float acc = 0.f;
        #pragma unroll 8
        for (int j=0;j<64;j++){
            float4 w = Wq4[row*256 + c4*64 + j];
            float4 q = q4[c4*64 + j];
            acc += w.x*q.x + w.y*q.y + w.z*q.z + w.w*q.w;
        }
        acc += __shfl_xor_sync(0xffffffffu, acc, 1);
        acc += __shfl_xor_sync(0xffffffffu, acc, 2);
        if (c4==0) qv[r] = acc + bq[row];
    }
    __syncthreads();
    {
        int c = tid&127, dh = tid>>7;
        float acc = 0.f;
        #pragma unroll 8
        for (int j=0;j<32;j++){
            int d = dh*32 + j;
            acc += qv[d] * Wk[(h*64+d)*1024 + es*128 + c];
        }
        if (dh==1) acc2[c] = acc;
        __syncthreads();
        if (dh==0)
            g_wqk[h*1024 + es*128 + c] = 0.125f*(acc + acc2[c]);
    }
    if (es==0 && tid==0){
        float c=0.f;
        for (int d=0;d<64;d++) c += qv[d]*bk[h*64+d];
        g_c[h] = 0.125f*c;
    }
}

// ---------------- K1: logits = w_qk·x + c (warp-private pipeline) ----------------
__global__ void __launch_bounds__(256,2) k_logits(const float4* __restrict__ x4){
    __shared__ float4 sxw[8][2][4][32];
    __shared__ float  sred[8][32][16];
    int tid = threadIdx.x, lane = tid&31, warp = tid>>5;
    int hg = lane>>3, ep = lane&7;
    ull wA[4][4], wB[4][4];
    {
        const float4* wq4 = (const float4*)g_wqk;
        #pragma unroll
        for (int k=0;k<4;k++){
            int F = warp*32 + k*8 + ep;
            #pragma unroll
            for (int hp=0;hp<4;hp++){
                float4 wv = wq4[(hg*4+hp)*256 + F];
                wA[k][hp] = pk2(wv.x,wv.y);
                wB[k][hp] = pk2(wv.z,wv.w);
            }
        }
    }
    int rowbase = blockIdx.x*32, b = rowbase>>12;
    bool hi4 = (lane&4)!=0, hi2 = (lane&2)!=0;

    #pragma unroll
    for (int r=0;r<4;r++)
        cpa16(&sxw[warp][0][r][lane], &x4[(rowbase+r)*256 + warp*32 + lane]);
    asm volatile("cp.async.commit_group;");

    for (int t=0;t<8;t++){
        if (t<7){
            int rb1 = rowbase + (t+1)*4;
            #pragma unroll
            for (int r=0;r<4;r++)
                cpa16(&sxw[warp][(t+1)&1][r][lane], &x4[(rb1+r)*256 + warp*32 + lane]);
            asm volatile("cp.async.commit_group;");
            asm volatile("cp.async.wait_group 1;");
        } else {
            asm volatile("cp.async.wait_group 0;");
        }
        __syncwarp();
        const ulonglong2* xs = (const ulonglong2*)&sxw[warp][t&1][0][0] + ep;
        ull acc[4][4];
        #pragma unroll
        for (int r=0;r<4;r++)
            #pragma unroll
            for (int hp=0;hp<4;hp++) acc[r][hp] = 0ULL;
        #pragma unroll
        for (int r=0;r<4;r++){
            #pragma unroll
            for (int k=0;k<4;k++){
                ulonglong2 xu = xs[r*32 + k*8];
                #pragma unroll
                for (int hp=0;hp<4;hp++){
                    ffma2(acc[r][hp], wA[k][hp], xu.x);
                    ffma2(acc[r][hp], wB[k][hp], xu.y);
                }
            }
        }
        #pragma unroll
        for (int r=0;r<4;r++){
            ull s0 = hi4 ? acc[r][0] : acc[r][2];
            s0 = __shfl_xor_sync(0xffffffffu, s0, 4);
            ull a0 = fadd2(hi4 ? acc[r][2] : acc[r][0], s0);
            ull s1 = hi4 ? acc[r][1] : acc[r][3];
            s1 = __shfl_xor_sync(0xffffffffu, s1, 4);
            ull a1 = fadd2(hi4 ? acc[r][3] : acc[r][1], s1);
            ull s2 = hi2 ? a0 : a1;
            s2 = __shfl_xor_sync(0xffffffffu, s2, 2);
            ull aa = fadd2(hi2 ? a1 : a0, s2);
            aa = fadd2(aa, __shfl_xor_sync(0xffffffffu, aa, 1));
            float2 f = upk(aa);
            if ((ep&1)==0) sred[warp][t*4+r][hg*4 + (ep>>1)] = f.x + f.y;
        }
        __syncwarp();
    }
    __syncthreads();
    {
        int h = tid>>5, row = tid&31;
        int sbase = (rowbase&4095) + row;
        #pragma unroll
        for (int hh=0; hh<2; hh++){
            int hc = h + hh*8;
            float s = g_c[hc];
            #pragma unroll
            for (int w=0;w<8;w++) s += sred[w][row][hc];
            g_logits[((b<<4)+hc)*4096 + sbase] = s;
        }
    }
}

// ---------------- K2: softmax over S + gumbel hard mask, per (b,h) ----------------
__global__ void __launch_bounds__(256) k_softmax(const float2* __restrict__ gu2){
    __shared__ float red[8];
    __shared__ float bc;
    int bid = blockIdx.x;                 // b*16+h
    int tid = threadIdx.x, lane = tid&31, warp = tid>>5;
    int base = bid*4096;
    float l[16];
    float m = -1e30f;
    #pragma unroll
    for (int j=0;j<16;j++){ l[j] = g_logits[base + tid + 256*j]; m = fmaxf(m, l[j]); }
    #pragma unroll
    for (int o=16;o;o>>=1) m = fmaxf(m, __shfl_xor_sync(0xffffffffu,m,o));
    if (lane==0) red[warp]=m;
    __syncthreads();
    if (tid==0){ float mm=red[0]; for(int i=1;i<8;i++) mm=fmaxf(mm,red[i]); bc=mm; }
    __syncthreads();
    m = bc;
    float ex[16]; float sum=0.f;
    #pragma unroll
    for (int j=0;j<16;j++){ ex[j]=__expf(l[j]-m); sum+=ex[j]; }
    sum = warp_sum(sum);
    if (lane==0) red[warp]=sum;
    __syncthreads();
    if (tid==0){ float ss=0.f; for(int i=0;i<8;i++) ss+=red[i]; bc=ss; }
    __syncthreads();
    float inv = 1.f/bc;
    float ps=0.f;
    #pragma unroll
    for (int j=0;j<16;j++){
        int s = tid+256*j;
        float prob = ex[j]*inv;
        float2 u = gu2[base+s];
        float g0 = -__logf(-__logf(u.x+1e-20f)+1e-20f);
        float g1 = -__logf(-__logf(u.y+1e-20f)+1e-20f);
        float A = (l[j]+g1 > g0) ? 1.f : 0.f;
        float pm = A*prob;
        g_A[base+s]=A; g_pm[base+s]=pm; ps+=pm;
    }
    ps = warp_sum(ps);
    if (lane==0) red[warp]=ps;
    __syncthreads();
    if (tid==0){ float ss=0.f; for(int i=0;i<8;i++) ss+=red[i]; g_psum[bid]=ss; }
}

// ---------------- K3: ctx partials, transposed pm packing, grid 296 ----------------
// Thread: 4 h-pairs (h, h+8) x 8 e-floats. pm pair-packed (NO dup) in smem:
// 2 broadcast LDS.128/si. x via 2 LDG.128/si, dup-packed in registers.
// 64 B/lane-si delivered vs 96 in R8. Grid 296 = 8 b x 37 chunks (~111 si):
// exactly 2 blocks/SM, zero wave-quantization waste.
__global__ void __launch_bounds__(256,2) k_ctx(const float4* __restrict__ x4,
                                               float* __restrict__ out){
    __shared__ __align__(16) ull sp[CSZ_MAX][8];   // (pm[h], pm[h+8]) pairs, 7 KB
    int tid = threadIdx.x;
    int b = blockIdx.x / 37, chunk = blockIdx.x % 37;
    int c0 = (chunk*4096)/37, c1 = ((chunk+1)*4096)/37;
    int csz = c1 - c0;                    // 110 or 111
    // stage pm pairs
    int slots = csz*8;
    #pragma unroll
    for (int i=0;i<4;i++){
        int idx = tid + 256*i;
        if (idx < slots){
            int si = idx>>3, j = idx&7;
            int s = c0 + si;
            float lo = g_pm[((b<<4)+j  )*4096 + s];
            float hi = g_pm[((b<<4)+j+8)*4096 + s];
            sp[si][j] = pk2(lo, hi);
        }
    }
    // fused masks/attn head-sums for this (b, si-range)
    if (tid < csz){
        int s = c0 + tid;
        float ms=0.f, as=0.f;
        #pragma unroll
        for (int h=0;h<16;h++){
            int off = ((b<<4)+h)*4096 + s;
            ms += g_A[off];
            as += g_pm[off];
        }
        out[8192 + b*4096 + s] = ms;
        out[8192 + 32768 + b*4096 + s] = as;
    }
    __syncthreads();
    int col = tid&127, oct = tid>>7;
    ull acc[4][8];
    #pragma unroll
    for (int j=0;j<4;j++)
        #pragma unroll
        for (int e=0;e<8;e++) acc[j][e] = 0ULL;
    #pragma unroll 8
    for (int si=0; si<csz; si++){
        int row = b*4096 + c0 + si;
        float4 xa = __ldg(&x4[row*256 + col]);
        float4 xb = __ldg(&x4[row*256 + 128 + col]);
        ulonglong2 pu01 = *(const ulonglong2*)&sp[si][oct*4];
        ulonglong2 pu23 = *(const ulonglong2*)&sp[si][oct*4+2];
        ull pu[4] = {pu01.x, pu01.y, pu23.x, pu23.y};
        ull xd[8];
        xd[0]=pk2(xa.x,xa.x); xd[1]=pk2(xa.y,xa.y);
        xd[2]=pk2(xa.z,xa.z); xd[3]=pk2(xa.w,xa.w);
        xd[4]=pk2(xb.x,xb.x); xd[5]=pk2(xb.y,xb.y);
        xd[6]=pk2(xb.z,xb.z); xd[7]=pk2(xb.w,xb.w);
        #pragma unroll
        for (int j=0;j<4;j++)
            #pragma unroll
            for (int e=0;e<8;e++)
                ffma2(acc[j][e], pu[j], xd[e]);
    }
    // epilogue: unpack pairs and store both head rows
    float4* p4 = (float4*)g_partial;
    int pbase = (b*37 + chunk)*16;
    #pragma unroll
    for (int j=0;j<4;j++){
        int hlo = oct*4 + j, hhi = hlo + 8;
        float2 f0 = upk(acc[j][0]), f1 = upk(acc[j][1]);
        float2 f2 = upk(acc[j][2]), f3 = upk(acc[j][3]);
        float2 f4v= upk(acc[j][4]), f5 = upk(acc[j][5]);
        float2 f6 = upk(acc[j][6]), f7 = upk(acc[j][7]);
        p4[(pbase+hlo)*256 + col]       = make_float4(f0.x,f1.x,f2.x,f3.x);
        p4[(pbase+hlo)*256 + 128 + col] = make_float4(f4v.x,f5.x,f6.x,f7.x);
        p4[(pbase+hhi)*256 + col]       = make_float4(f0.y,f1.y,f2.y,f3.y);
        p4[(pbase+hhi)*256 + 128 + col] = make_float4(f4v.y,f5.y,f6.y,f7.y);
    }
}

// ---------------- K3r: deterministic reduction of ctx partials (float4) ----------------
__global__ void __launch_bounds__(256) k_ctxr(){
    int f4 = blockIdx.x*256 + threadIdx.x;   // 0..32767 float4 of ctx
    int b = f4>>12, rem = f4&4095;
    const float4* p4 = (const float4*)g_partial;
    float4 s = make_float4(0,0,0,0);
    #pragma unroll
    for (int c=0;c<NCHUNK;c++){
        float4 v = p4[(b*NCHUNK+c)*4096 + rem];
        s.x+=v.x; s.y+=v.y; s.z+=v.z; s.w+=v.w;
    }
    ((float4*)g_ctx)[f4] = s;
}

// ---------------- K4a: hidden = Wv·ctx + bv*psum ----------------
__global__ void __launch_bounds__(256) k_hidden(const float4* __restrict__ Wv4,
                                                const float*  __restrict__ bv){
    int lane = threadIdx.x&31, warp = threadIdx.x>>5;
    int row = blockIdx.x*8+warp;
    int h = row>>6;
    float4 w[8];
    #pragma unroll
    for (int k=0;k<8;k++) w[k] = Wv4[row*256 + lane + 32*k];
    const float4* c4 = (const float4*)g_ctx;
    float acc[8];
    #pragma unroll
    for (int b=0;b<8;b++){
        float s=0.f;
        #pragma unroll
        for (int k=0;k<8;k++){
            float4 c = c4[((b<<4)+h)*256 + lane + 32*k];
            s += w[k].x*c.x + w[k].y*c.y + w[k].z*c.z + w[k].w*c.w;
        }
        acc[b]=s;
    }
    #pragma unroll
    for (int o=16;o;o>>=1)
        #pragma unroll
        for (int b=0;b<8;b++) acc[b] += __shfl_xor_sync(0xffffffffu, acc[b], o);
    if (lane==0){
        float bvr = bv[row];
        #pragma unroll
        for (int b=0;b<8;b++) g_hidden[b*1024+row] = acc[b] + bvr*g_psum[(b<<4)+h];
    }
}

// ---------------- K4c: fused LN + act = relu(ln(hidden) @ W1^T + b1) ----------------
__global__ void __launch_bounds__(256) k_mlp1(const float4* __restrict__ W14,
                                              const float*  __restrict__ b1,
                                              const float4* __restrict__ lg4,
                                              const float4* __restrict__ lb4){
    __shared__ float4 hls[2048];
    int tid = threadIdx.x, lane=tid&31, warp=tid>>5;
    {
        int b = warp;
        const float4* h4 = (const float4*)g_hidden;
        float4 v[8];
        float s = 0.f;
        #pragma unroll
        for (int k=0;k<8;k++){
            v[k] = h4[b*256 + lane + 32*k];
            s += v[k].x + v[k].y + v[k].z + v[k].w;
        }
        s = warp_sum(s);
        float mu = s * (1.f/1024.f);
        float q = 0.f;
        #pragma unroll
        for (int k=0;k<8;k++){
            float dx=v[k].x-mu, dy=v[k].y-mu, dz=v[k].z-mu, dw=v[k].w-mu;
            q += dx*dx + dy*dy + dz*dz + dw*dw;
        }
        q = warp_sum(q);
        float rstd = rsqrtf(q*(1.f/1024.f) + 1e-5f);
        #pragma unroll
        for (int k=0;k<8;k++){
            float4 g = lg4[lane+32*k], bb = lb4[lane+32*k];
            hls[b*256+lane+32*k] = make_float4(
                (v[k].x-mu)*rstd*g.x + bb.x,
                (v[k].y-mu)*rstd*g.y + bb.y,
                (v[k].z-mu)*rstd*g.z + bb.z,
                (v[k].w-mu)*rstd*g.w + bb.w);
        }
    }
    __syncthreads();
    int row = blockIdx.x*8+warp;
    float4 w[8];
    #pragma unroll
    for (int k=0;k<8;k++) w[k]=W14[row*256+lane+32*k];
    float acc[8];
    #pragma unroll
    for (int b=0;b<8;b++){
        float s=0.f;
        #pragma unroll
        for (int k=0;k<8;k++){
            float4 hv = hls[b*256 + lane + 32*k];
            s += w[k].x*hv.x + w[k].y*hv.y + w[k].z*hv.z + w[k].w*hv.w;
        }
        acc[b]=s;
    }
    #pragma unroll
    for (int o=16;o;o>>=1)
        #pragma unroll
        for (int b=0;b<8;b++) acc[b] += __shfl_xor_sync(0xffffffffu, acc[b], o);
    if (lane==0){
        float bb = b1[row];
        #pragma unroll
        for (int b=0;b<8;b++) g_act[b*4096+row] = fmaxf(acc[b]+bb, 0.f);
    }
}

// ---------------- K4d: out = act @ W2^T + b2 ----------------
__global__ void __launch_bounds__(256) k_mlp2(const float4* __restrict__ W24,
                                              const float*  __restrict__ b2,
                                              float* __restrict__ out){
    extern __shared__ float4 as4[];
    int tid=threadIdx.x, lane=tid&31, warp=tid>>5;
    const float4* a4 = (const float4*)g_act;
    #pragma unroll
    for (int i=0;i<32;i++) as4[tid+256*i] = a4[tid+256*i];
    __syncthreads();
    int row = blockIdx.x*8+warp;
    float acc[8];
    #pragma unroll
    for (int b=0;b<8;b++) acc[b]=0.f;
    #pragma unroll 4
    for (int k=0;k<32;k++){
        float4 w = W24[row*1024 + lane + 32*k];
        #pragma unroll
        for (int b=0;b<8;b++){
            float4 av = as4[b*1024 + lane + 32*k];
            acc[b] += w.x*av.x + w.y*av.y + w.z*av.z + w.w*av.w;
        }
    }
    #pragma unroll
    for (int o=16;o;o>>=1)
        #pragma unroll
        for (int b=0;b<8;b++) acc[b] += __shfl_xor_sync(0xffffffffu, acc[b], o);
    if (lane==0){
        float bb = b2[row];
        #pragma unroll
        for (int b=0;b<8;b++) out[b*1024+row] = acc[b] + bb;
    }
}

extern "C" void kernel_launch(void* const* d_in, const int* in_sizes, int n_in,
                              void* d_out, int out_size){
    const float* x     = (const float*)d_in[0];
    const float* gu    = (const float*)d_in[1];
    const float* query = (const float*)d_in[2];
    const float* Wq    = (const float*)d_in[3];
    const float* bq    = (const float*)d_in[4];
    const float* Wk    = (const float*)d_in[5];
    const float* bk    = (const float*)d_in[6];
    const float* Wv    = (const float*)d_in[7];
    const float* bv    = (const float*)d_in[8];
    const float* ln_g  = (const float*)d_in[9];
    const float* ln_b  = (const float*)d_in[10];
    const float* W1    = (const float*)d_in[11];
    const float* b1    = (const float*)d_in[12];
    const float* W2    = (const float*)d_in[13];
    const float* b2    = (const float*)d_in[14];
    float* out = (float*)d_out;

    cudaFuncSetAttribute(k_mlp2, cudaFuncAttributeMaxDynamicSharedMemorySize, 131072);

    k_wqkf   <<<128,256>>>((const float4*)Wq, (const float4*)query, bq,
                           Wk, bk);                                         // 1
    k_logits <<<1024,256>>>((const float4*)x);                              // 2
    k_softmax<<<128,256>>>((const float2*)gu);                              // 3
    k_ctx    <<<296,256>>>((const float4*)x, out);                          // 4 (profiled)
    k_ctxr   <<<128,256>>>();                                               // 5
    k_hidden <<<128,256>>>((const float4*)Wv, bv);                          // 6
    k_mlp1   <<<512,256>>>((const float4*)W1, b1,
                           (const float4*)ln_g, (const float4*)ln_b);       // 7
    k_mlp2   <<<128,256,131072>>>((const float4*)W2, b2, out);              // 8
}